// round 8
// baseline (speedup 1.0000x reference)
#include <cuda_runtime.h>
#include <cuda_fp16.h>
#include <cstdint>

#define S_LEN   8192
#define B_MAX   512
#define THREADS 256
#define CHUNK   32            // S_LEN / THREADS
#define EPT     8             // elements per thread in stream kernel
#define BIGI    (1 << 20)

// Scratch (device globals: allocation-free rule)
__device__ __half   g_ce[B_MAX * S_LEN];     // 8.4 MB
__device__ uint8_t  g_pl[B_MAX * S_LEN];     // 4.2 MB
__device__ float    g_sum[B_MAX];
__device__ float    g_cnt[B_MAX];
__device__ int      g_ctr;                   // zero-init; last CTA resets to 0

// ---------------------------------------------------------------------------
// Kernel A: pure streaming — argmax + weighted CE + packed flags to scratch
// ---------------------------------------------------------------------------
__global__ void __launch_bounds__(THREADS)
stream_kernel(const float4* __restrict__ logits, const int4* __restrict__ labels4,
              int total8) {
    int idx = blockIdx.x * blockDim.x + threadIdx.x;
    if (idx >= total8) return;

    const float4* lp = logits + (size_t)idx * EPT;
    int4 la0 = labels4[idx * 2 + 0];
    int4 la1 = labels4[idx * 2 + 1];
    int labs[EPT] = {la0.x, la0.y, la0.z, la0.w, la1.x, la1.y, la1.z, la1.w};

    float4 v[EPT];
#pragma unroll
    for (int j = 0; j < EPT; j++) v[j] = lp[j];    // batch loads -> high MLP

    uint32_t ceu[EPT / 2];
    uint32_t plu[EPT / 4] = {0, 0};
#pragma unroll
    for (int j = 0; j < EPT; j++) {
        float x = v[j].x, y = v[j].y, z = v[j].z, w = v[j].w;
        int pred = 0; float m = x;
        if (y > m) { m = y; pred = 1; }
        if (z > m) { m = z; pred = 2; }
        if (w > m) { m = w; pred = 3; }
        int  lab   = labs[j];
        bool valid = (lab != -100);
        int  lb    = valid ? lab : 0;
        float ce = 0.0f;
        if (valid) {
            float e   = __expf(x - m) + __expf(y - m) + __expf(z - m) + __expf(w - m);
            float lse = m + __logf(e);
            float xl  = (lb == 0) ? x : (lb == 1) ? y : (lb == 2) ? z : w;
            ce = (lse - xl) * ((lb >= 2) ? 30.0f : 1.0f);
        }
        unsigned hu = (unsigned)__half_as_ushort(__float2half(ce));
        if (j & 1) ceu[j >> 1] |= hu << 16; else ceu[j >> 1] = hu;
        plu[j >> 2] |= ((unsigned)(pred | (lb << 2) | (valid ? 16 : 0))) << ((j & 3) * 8);
    }
    reinterpret_cast<uint4*>(g_ce)[idx] = make_uint4(ceu[0], ceu[1], ceu[2], ceu[3]);
    reinterpret_cast<uint2*>(g_pl)[idx] = make_uint2(plu[0], plu[1]);
}

// ---------------------------------------------------------------------------
// Kernel B: per-row scans + state machine + final reduction (last CTA)
// ---------------------------------------------------------------------------
__global__ void __launch_bounds__(THREADS)
scan_kernel(float* __restrict__ out, int Bn) {
    const int row = blockIdx.x;
    const int tid = threadIdx.x;
    const int base = tid * CHUNK;
    const size_t roff = (size_t)row * S_LEN;

    __shared__ int sc[10][THREADS];

    // Load this thread's 32 packed bytes (2 x LDG.128, fully coalesced at sector level)
    uint4 p0 = reinterpret_cast<const uint4*>(g_pl + roff + base)[0];
    uint4 p1 = reinterpret_cast<const uint4*>(g_pl + roff + base)[1];
    uint32_t plw[8] = {p0.x, p0.y, p0.z, p0.w, p1.x, p1.y, p1.z, p1.w};

    // ---------------- Phase 1: per-thread chunk summaries ----------------
    int encP = -1, encL = -1;
    int tLast2 = -1, tLast3 = -1, pLast2 = -1, pLast3 = -1;
    int tFirst2 = BIGI, tFirst3 = BIGI, pFirst2 = BIGI, pFirst3 = BIGI;
#pragma unroll
    for (int t = 0; t < CHUNK; t++) {
        unsigned pb = (plw[t >> 2] >> ((t & 3) * 8)) & 0xffu;
        int pred = pb & 3, lb = (pb >> 2) & 3;
        bool valid = (pb & 16) != 0;
        int g = base + t;
        if (valid) { encP = (g << 1) | (pred & 1); encL = (g << 1) | (lb & 1); }
        if (lb == 2)   { tLast2 = g; if (tFirst2 == BIGI) tFirst2 = g; }
        if (lb == 3)   { tLast3 = g; if (tFirst3 == BIGI) tFirst3 = g; }
        if (pred == 2) { pLast2 = g; if (pFirst2 == BIGI) pFirst2 = g; }
        if (pred == 3) { pLast3 = g; if (pFirst3 == BIGI) pFirst3 = g; }
    }

    // ---------------- Phase 2: 10 fused Hillis-Steele block scans ----------------
    sc[0][tid] = encP;    sc[1][tid] = encL;
    sc[2][tid] = tLast2;  sc[3][tid] = tLast3;  sc[4][tid] = pLast2;  sc[5][tid] = pLast3;
    sc[6][tid] = tFirst2; sc[7][tid] = tFirst3; sc[8][tid] = pFirst2; sc[9][tid] = pFirst3;
    __syncthreads();
    for (int d = 1; d < THREADS; d <<= 1) {
        int up0 = 0, up1 = 0, up2 = 0, up3 = 0, up4 = 0, up5 = 0;
        int dn0 = 0, dn1 = 0, dn2 = 0, dn3 = 0;
        bool hu = (tid >= d), hd = (tid + d < THREADS);
        if (hu) {
            up0 = sc[0][tid - d]; up1 = sc[1][tid - d]; up2 = sc[2][tid - d];
            up3 = sc[3][tid - d]; up4 = sc[4][tid - d]; up5 = sc[5][tid - d];
        }
        if (hd) {
            dn0 = sc[6][tid + d]; dn1 = sc[7][tid + d];
            dn2 = sc[8][tid + d]; dn3 = sc[9][tid + d];
        }
        __syncthreads();
        if (hu) {
            sc[0][tid] = max(sc[0][tid], up0); sc[1][tid] = max(sc[1][tid], up1);
            sc[2][tid] = max(sc[2][tid], up2); sc[3][tid] = max(sc[3][tid], up3);
            sc[4][tid] = max(sc[4][tid], up4); sc[5][tid] = max(sc[5][tid], up5);
        }
        if (hd) {
            sc[6][tid] = min(sc[6][tid], dn0); sc[7][tid] = min(sc[7][tid], dn1);
            sc[8][tid] = min(sc[8][tid], dn2); sc[9][tid] = min(sc[9][tid], dn3);
        }
        __syncthreads();
    }
    int epm = tid ? sc[0][tid - 1] : -1;
    int etm = tid ? sc[1][tid - 1] : -1;
    int lT2 = tid ? sc[2][tid - 1] : -1;  if (lT2 < 0) lT2 = -BIGI;
    int lT3 = tid ? sc[3][tid - 1] : -1;  if (lT3 < 0) lT3 = -BIGI;
    int lP2 = tid ? sc[4][tid - 1] : -1;  if (lP2 < 0) lP2 = -BIGI;
    int lP3 = tid ? sc[5][tid - 1] : -1;  if (lP3 < 0) lP3 = -BIGI;
    bool hasT2 = sc[2][THREADS - 1] >= 0;
    bool hasT3 = sc[3][THREADS - 1] >= 0;
    bool hasP2 = sc[4][THREADS - 1] >= 0;
    bool hasP3 = sc[5][THREADS - 1] >= 0;
    int nT2 = (tid < THREADS - 1) ? sc[6][tid + 1] : BIGI;
    int nT3 = (tid < THREADS - 1) ? sc[7][tid + 1] : BIGI;
    int nP2 = (tid < THREADS - 1) ? sc[8][tid + 1] : BIGI;
    int nP3 = (tid < THREADS - 1) ? sc[9][tid + 1] : BIGI;

    // ------------ Phase 3a: backward walk (bwd distances, 4x4 bits/pos) ------------
    uint32_t bw[CHUNK / 2];
#pragma unroll
    for (int t = CHUNK - 1; t >= 0; t--) {
        unsigned pb = (plw[t >> 2] >> ((t & 3) * 8)) & 0xffu;
        int pred = pb & 3, lb = (pb >> 2) & 3;
        int g = base + t;
        if (lb == 2)   nT2 = g;
        if (lb == 3)   nT3 = g;
        if (pred == 2) nP2 = g;
        if (pred == 3) nP3 = g;
        unsigned dT2 = min(nT2 - g, 15), dT3 = min(nT3 - g, 15);
        unsigned dP2 = min(nP2 - g, 15), dP3 = min(nP3 - g, 15);
        unsigned pack = dT2 | (dT3 << 4) | (dP2 << 8) | (dP3 << 12);
        if (t & 1) bw[t >> 1]  = pack << 16;
        else       bw[t >> 1] |= pack;
    }

    // ------------ Phase 3b: forward walk (state machine + multipliers) ------------
    // CE loads: 4 x LDG.128 of contiguous 64B per thread (L2-resident scratch)
    uint4 c0 = reinterpret_cast<const uint4*>(g_ce + roff + base)[0];
    uint4 c1 = reinterpret_cast<const uint4*>(g_ce + roff + base)[1];
    uint4 c2 = reinterpret_cast<const uint4*>(g_ce + roff + base)[2];
    uint4 c3 = reinterpret_cast<const uint4*>(g_ce + roff + base)[3];
    uint32_t ceu[16] = {c0.x, c0.y, c0.z, c0.w, c1.x, c1.y, c1.z, c1.w,
                        c2.x, c2.y, c2.z, c2.w, c3.x, c3.y, c3.z, c3.w};

    int pm = (epm < 0) ? 0 : (epm & 1);
    int tm = (etm < 0) ? 0 : (etm & 1);
    float acc = 0.0f;
    int   cnt = 0;
#pragma unroll
    for (int t = 0; t < CHUNK; t++) {
        unsigned pb = (plw[t >> 2] >> ((t & 3) * 8)) & 0xffu;
        int pred = pb & 3, lb = (pb >> 2) & 3;
        bool valid = (pb & 16) != 0;
        int g = base + t;
        float mult = 1.0f;
        if (valid) {
            if ((pred == 2 && pm == 0) || (pred == 3 && pm == 1)) mult = 100.0f;  // INV_PEN
            if ((lb == 2 && tm == 1 && pred == 2) ||
                (lb == 3 && tm == 0 && pred == 3)) mult *= 0.1f;                  // bonus
        }
        if (lb == 2)   lT2 = g;
        if (lb == 3)   lT3 = g;
        if (pred == 2) lP2 = g;
        if (pred == 3) lP3 = g;
        unsigned pk = (bw[t >> 1] >> ((t & 1) * 16)) & 0xffffu;
        if (pred == 2) {
            int d = min(g - lT2, (int)(pk & 15));
            float mp = hasT2 ? ((d == 0) ? 0.1f
                       : (d <= 5) ? ((d == 1) ? 0.7f : (d == 2) ? 0.49f : (d == 3) ? 0.343f
                                    : (d == 4) ? 0.2401f : 0.16807f)
                       : 10.0f) : 20.0f;
            mult *= mp;
        }
        if (pred == 3) {
            int d = min(g - lT3, (int)((pk >> 4) & 15));
            float mp = hasT3 ? ((d == 0) ? 0.1f
                       : (d <= 5) ? ((d == 1) ? 0.7f : (d == 2) ? 0.49f : (d == 3) ? 0.343f
                                    : (d == 4) ? 0.2401f : 0.16807f)
                       : 10.0f) : 20.0f;
            mult *= mp;
        }
        if (lb == 2) {
            int d = min(g - lP2, (int)((pk >> 8) & 15));
            mult *= hasP2 ? ((d > 5) ? 2.0f : 1.0f) : 3.0f;
        }
        if (lb == 3) {
            int d = min(g - lP3, (int)((pk >> 12) & 15));
            mult *= hasP3 ? ((d > 5) ? 2.0f : 1.0f) : 3.0f;
        }
        if (valid) {
            float ce = __half2float(__ushort_as_half((unsigned short)((ceu[t >> 1] >> ((t & 1) * 16)) & 0xffffu)));
            acc += ce * mult;
            cnt++;
            pm = pred & 1;
            tm = lb & 1;
        }
    }

    // ---------------- Block reduction (deterministic) ----------------
    __syncthreads();
    float* rsum = (float*)&sc[0][0];
    float* rcnt = (float*)&sc[4][0];
    rsum[tid] = acc;
    rcnt[tid] = (float)cnt;
    __syncthreads();
    for (int d = THREADS / 2; d > 0; d >>= 1) {
        if (tid < d) { rsum[tid] += rsum[tid + d]; rcnt[tid] += rcnt[tid + d]; }
        __syncthreads();
    }

    // ---------------- Last-CTA global reduction (deterministic order) ----------------
    __shared__ int s_last;
    if (tid == 0) {
        g_sum[row] = rsum[0];
        g_cnt[row] = rcnt[0];
        __threadfence();
        int old = atomicAdd(&g_ctr, 1);
        s_last = (old == Bn - 1) ? 1 : 0;
    }
    __syncthreads();
    if (s_last) {
        __threadfence();
        float ls = 0.0f, lc = 0.0f;
        for (int r = tid; r < Bn; r += THREADS) { ls += g_sum[r]; lc += g_cnt[r]; }
        rsum[tid] = ls; rcnt[tid] = lc;
        __syncthreads();
        for (int d = THREADS / 2; d > 0; d >>= 1) {
            if (tid < d) { rsum[tid] += rsum[tid + d]; rcnt[tid] += rcnt[tid + d]; }
            __syncthreads();
        }
        if (tid == 0) {
            out[0] = rsum[0] / fmaxf(rcnt[0], 1.0f);
            g_ctr = 0;   // reset for next graph replay
        }
    }
}

extern "C" void kernel_launch(void* const* d_in, const int* in_sizes, int n_in,
                              void* d_out, int out_size) {
    const float* logits = (const float*)d_in[0];
    const int*   labels = (const int*)d_in[1];
    int Bn = in_sizes[1] / S_LEN;
    if (Bn > B_MAX) Bn = B_MAX;
    int total8 = Bn * (S_LEN / EPT);                 // threads in stream kernel
    int gridA  = (total8 + THREADS - 1) / THREADS;
    stream_kernel<<<gridA, THREADS>>>((const float4*)logits, (const int4*)labels, total8);
    scan_kernel<<<Bn, THREADS>>>((float*)d_out, Bn);
}

// round 9
// speedup vs baseline: 2.6160x; 2.6160x over previous
#include <cuda_runtime.h>
#include <cuda_fp16.h>
#include <cstdint>

#define S_LEN   8192
#define B_MAX   512
#define NT      1024                 // threads per row-CTA
#define CHUNK   (S_LEN / NT)         // 8
#define BIGI    (1 << 20)
#define FULL    0xffffffffu

__device__ float g_sum[B_MAX];
__device__ float g_cnt[B_MAX];
__device__ int   g_ctr;              // zero-init; last CTA resets to 0

__device__ __forceinline__ int warpInclMax(int v, int lane) {
#pragma unroll
    for (int d = 1; d < 32; d <<= 1) {
        int o = __shfl_up_sync(FULL, v, d);
        if (lane >= d) v = max(v, o);
    }
    return v;
}
__device__ __forceinline__ int warpInclMinRev(int v, int lane) {
#pragma unroll
    for (int d = 1; d < 32; d <<= 1) {
        int o = __shfl_down_sync(FULL, v, d);
        if (lane < 32 - d) v = min(v, o);
    }
    return v;
}

__global__ void __launch_bounds__(NT)
loss_fused(const float4* __restrict__ logits, const int* __restrict__ labels,
           float* __restrict__ out, int Bn) {
    const int row  = blockIdx.x;
    const int tid  = threadIdx.x;
    const int lane = tid & 31;
    const int wid  = tid >> 5;
    const int base = tid * CHUNK;

    __shared__ int   agg[10][32];
    __shared__ float rs[32], rc[32];
    __shared__ int   s_last;

    // ================= Phase 0: stream own 8 positions, keep in regs =================
    const float4* lrow = logits + (size_t)row * S_LEN + base;
    const int4*   lab4 = reinterpret_cast<const int4*>(labels + (size_t)row * S_LEN + base);

    uint32_t ceu[CHUNK / 2];          // fp16 CE, 2 per word
    uint32_t plw[CHUNK / 4] = {0, 0}; // packed pred|lb<<2|valid<<4 bytes
#pragma unroll
    for (int h = 0; h < 2; h++) {
        float4 v[4];
        int4 la = lab4[h];
        int labs[4] = {la.x, la.y, la.z, la.w};
#pragma unroll
        for (int j = 0; j < 4; j++) v[j] = lrow[h * 4 + j];   // batched -> MLP
#pragma unroll
        for (int j = 0; j < 4; j++) {
            float x = v[j].x, y = v[j].y, z = v[j].z, w = v[j].w;
            int pred = 0; float m = x;
            if (y > m) { m = y; pred = 1; }
            if (z > m) { m = z; pred = 2; }
            if (w > m) { m = w; pred = 3; }
            int  lab   = labs[j];
            bool valid = (lab != -100);
            int  lb    = valid ? lab : 0;
            float ce = 0.0f;
            if (valid) {
                float e   = __expf(x - m) + __expf(y - m) + __expf(z - m) + __expf(w - m);
                float lse = m + __logf(e);
                float xl  = (lb == 0) ? x : (lb == 1) ? y : (lb == 2) ? z : w;
                ce = (lse - xl) * ((lb >= 2) ? 30.0f : 1.0f);
            }
            int t = h * 4 + j;
            unsigned hu = (unsigned)__half_as_ushort(__float2half(ce));
            if (t & 1) ceu[t >> 1] |= hu << 16; else ceu[t >> 1] = hu;
            plw[h] |= ((unsigned)(pred | (lb << 2) | (valid ? 16 : 0))) << (j * 8);
        }
    }

    // ================= Phase 1: per-thread chunk summaries =================
    int encP = -1, encL = -1;
    int tLast2 = -1, tLast3 = -1, pLast2 = -1, pLast3 = -1;
    int tFirst2 = BIGI, tFirst3 = BIGI, pFirst2 = BIGI, pFirst3 = BIGI;
#pragma unroll
    for (int t = 0; t < CHUNK; t++) {
        unsigned pb = (plw[t >> 2] >> ((t & 3) * 8)) & 0xffu;
        int pred = pb & 3, lb = (pb >> 2) & 3;
        bool valid = (pb & 16) != 0;
        int g = base + t;
        if (valid) { encP = (g << 1) | (pred & 1); encL = (g << 1) | (lb & 1); }
        if (lb == 2)   { tLast2 = g; if (tFirst2 == BIGI) tFirst2 = g; }
        if (lb == 3)   { tLast3 = g; if (tFirst3 == BIGI) tFirst3 = g; }
        if (pred == 2) { pLast2 = g; if (pFirst2 == BIGI) pFirst2 = g; }
        if (pred == 3) { pLast3 = g; if (pFirst3 == BIGI) pFirst3 = g; }
    }

    // ================= Phase 2: warp scans + cross-warp scan =================
    // max-quantities (prefix), min-quantities (suffix)
    int qmax[6] = {encP, encL, tLast2, tLast3, pLast2, pLast3};
    int qmin[4] = {tFirst2, tFirst3, pFirst2, pFirst3};
    int exMax[6], exMin[4];
#pragma unroll
    for (int k = 0; k < 6; k++) {
        int incl = warpInclMax(qmax[k], lane);
        int ex   = __shfl_up_sync(FULL, incl, 1);
        exMax[k] = (lane == 0) ? -1 : ex;
        if (lane == 31) agg[k][wid] = incl;          // warp total
    }
#pragma unroll
    for (int k = 0; k < 4; k++) {
        int incl = warpInclMinRev(qmin[k], lane);
        int ex   = __shfl_down_sync(FULL, incl, 1);
        exMin[k] = (lane == 31) ? BIGI : ex;
        if (lane == 0) agg[6 + k][wid] = incl;       // warp total
    }
    __syncthreads();
    // cross-warp: every warp redundantly scans the 32 aggregates
    int crossMax[6], crossMin[4];
    bool has[4];
#pragma unroll
    for (int k = 0; k < 6; k++) {
        int a  = agg[k][lane];
        int ai = warpInclMax(a, lane);
        int src = (wid == 0) ? 0 : (wid - 1);
        int c  = __shfl_sync(FULL, ai, src);
        crossMax[k] = (wid == 0) ? -1 : c;
    }
#pragma unroll
    for (int k = 0; k < 4; k++) {
        int a  = agg[6 + k][lane];
        int ai = warpInclMinRev(a, lane);
        int src = (wid == 31) ? 31 : (wid + 1);
        int c  = __shfl_sync(FULL, ai, src);
        crossMin[k] = (wid == 31) ? BIGI : c;
        has[k] = (__shfl_sync(FULL, ai, 0) < BIGI);  // block-wide any-occurrence
    }

    int epm = max(exMax[0], crossMax[0]);
    int etm = max(exMax[1], crossMax[1]);
    int lT2 = max(exMax[2], crossMax[2]); if (lT2 < 0) lT2 = -BIGI;
    int lT3 = max(exMax[3], crossMax[3]); if (lT3 < 0) lT3 = -BIGI;
    int lP2 = max(exMax[4], crossMax[4]); if (lP2 < 0) lP2 = -BIGI;
    int lP3 = max(exMax[5], crossMax[5]); if (lP3 < 0) lP3 = -BIGI;
    int nT2 = min(exMin[0], crossMin[0]);
    int nT3 = min(exMin[1], crossMin[1]);
    int nP2 = min(exMin[2], crossMin[2]);
    int nP3 = min(exMin[3], crossMin[3]);
    bool hasT2 = has[0], hasT3 = has[1], hasP2 = has[2], hasP3 = has[3];

    // ============ Phase 3a: backward walk (bwd distances, 4x4 bits/pos) ============
    uint32_t bw[CHUNK / 2];
#pragma unroll
    for (int t = CHUNK - 1; t >= 0; t--) {
        unsigned pb = (plw[t >> 2] >> ((t & 3) * 8)) & 0xffu;
        int pred = pb & 3, lb = (pb >> 2) & 3;
        int g = base + t;
        if (lb == 2)   nT2 = g;
        if (lb == 3)   nT3 = g;
        if (pred == 2) nP2 = g;
        if (pred == 3) nP3 = g;
        unsigned dT2 = min(nT2 - g, 15), dT3 = min(nT3 - g, 15);
        unsigned dP2 = min(nP2 - g, 15), dP3 = min(nP3 - g, 15);
        unsigned pack = dT2 | (dT3 << 4) | (dP2 << 8) | (dP3 << 12);
        if (t & 1) bw[t >> 1]  = pack << 16;
        else       bw[t >> 1] |= pack;
    }

    // ============ Phase 3b: forward walk (state machine + multipliers) ============
    int pm = (epm < 0) ? 0 : (epm & 1);
    int tm = (etm < 0) ? 0 : (etm & 1);
    float acc = 0.0f;
    int   cnt = 0;
#pragma unroll
    for (int t = 0; t < CHUNK; t++) {
        unsigned pb = (plw[t >> 2] >> ((t & 3) * 8)) & 0xffu;
        int pred = pb & 3, lb = (pb >> 2) & 3;
        bool valid = (pb & 16) != 0;
        int g = base + t;
        float mult = 1.0f;
        if (valid) {
            if ((pred == 2 && pm == 0) || (pred == 3 && pm == 1)) mult = 100.0f;  // INV_PEN
            if ((lb == 2 && tm == 1 && pred == 2) ||
                (lb == 3 && tm == 0 && pred == 3)) mult *= 0.1f;                  // bonus
        }
        if (lb == 2)   lT2 = g;
        if (lb == 3)   lT3 = g;
        if (pred == 2) lP2 = g;
        if (pred == 3) lP3 = g;
        unsigned pk = (bw[t >> 1] >> ((t & 1) * 16)) & 0xffffu;
        if (pred == 2) {
            int d = min(g - lT2, (int)(pk & 15));
            float mp = hasT2 ? ((d == 0) ? 0.1f
                       : (d <= 5) ? ((d == 1) ? 0.7f : (d == 2) ? 0.49f : (d == 3) ? 0.343f
                                    : (d == 4) ? 0.2401f : 0.16807f)
                       : 10.0f) : 20.0f;
            mult *= mp;
        }
        if (pred == 3) {
            int d = min(g - lT3, (int)((pk >> 4) & 15));
            float mp = hasT3 ? ((d == 0) ? 0.1f
                       : (d <= 5) ? ((d == 1) ? 0.7f : (d == 2) ? 0.49f : (d == 3) ? 0.343f
                                    : (d == 4) ? 0.2401f : 0.16807f)
                       : 10.0f) : 20.0f;
            mult *= mp;
        }
        if (lb == 2) {
            int d = min(g - lP2, (int)((pk >> 8) & 15));
            mult *= hasP2 ? ((d > 5) ? 2.0f : 1.0f) : 3.0f;
        }
        if (lb == 3) {
            int d = min(g - lP3, (int)((pk >> 12) & 15));
            mult *= hasP3 ? ((d > 5) ? 2.0f : 1.0f) : 3.0f;
        }
        if (valid) {
            float ce = __half2float(__ushort_as_half(
                (unsigned short)((ceu[t >> 1] >> ((t & 1) * 16)) & 0xffffu)));
            acc += ce * mult;
            cnt++;
            pm = pred & 1;
            tm = lb & 1;
        }
    }

    // ================= Block reduction (warp shuffles, deterministic) =================
#pragma unroll
    for (int d = 16; d > 0; d >>= 1) {
        acc += __shfl_down_sync(FULL, acc, d);
        cnt += __shfl_down_sync(FULL, cnt, d);
    }
    if (lane == 0) { rs[wid] = acc; rc[wid] = (float)cnt; }
    __syncthreads();
    if (wid == 0) {
        float a = rs[lane], c = rc[lane];
#pragma unroll
        for (int d = 16; d > 0; d >>= 1) {
            a += __shfl_down_sync(FULL, a, d);
            c += __shfl_down_sync(FULL, c, d);
        }
        if (lane == 0) {
            g_sum[row] = a;
            g_cnt[row] = c;
            __threadfence();
            int old = atomicAdd(&g_ctr, 1);
            s_last = (old == Bn - 1) ? 1 : 0;
        }
    }
    __syncthreads();

    // ================= Last-CTA global reduction (deterministic order) =================
    if (s_last) {
        __threadfence();
        float ls = 0.0f, lc = 0.0f;
        for (int r = tid; r < Bn; r += NT) { ls += g_sum[r]; lc += g_cnt[r]; }
#pragma unroll
        for (int d = 16; d > 0; d >>= 1) {
            ls += __shfl_down_sync(FULL, ls, d);
            lc += __shfl_down_sync(FULL, lc, d);
        }
        __syncthreads();                 // rs/rc reuse
        if (lane == 0) { rs[wid] = ls; rc[wid] = lc; }
        __syncthreads();
        if (wid == 0) {
            float a = rs[lane], c = rc[lane];
#pragma unroll
            for (int d = 16; d > 0; d >>= 1) {
                a += __shfl_down_sync(FULL, a, d);
                c += __shfl_down_sync(FULL, c, d);
            }
            if (lane == 0) {
                out[0] = a / fmaxf(c, 1.0f);
                g_ctr = 0;               // reset for next graph replay
            }
        }
    }
}

extern "C" void kernel_launch(void* const* d_in, const int* in_sizes, int n_in,
                              void* d_out, int out_size) {
    const float* logits = (const float*)d_in[0];
    const int*   labels = (const int*)d_in[1];
    int Bn = in_sizes[1] / S_LEN;
    if (Bn > B_MAX) Bn = B_MAX;
    loss_fused<<<Bn, NT>>>((const float4*)logits, labels, (float*)d_out, Bn);
}

// round 10
// speedup vs baseline: 4.1078x; 1.5702x over previous
#include <cuda_runtime.h>
#include <cuda_fp16.h>
#include <cstdint>

#define S_LEN   8192
#define B_MAX   512
#define NT      1024                 // threads per row-CTA
#define CHUNK   (S_LEN / NT)         // 8
#define FULL    0xffffffffu

__device__ float g_sum[B_MAX];
__device__ float g_cnt[B_MAX];
__device__ int   g_ctr;              // zero-init; last CTA resets to 0

__device__ __forceinline__ int warpInclMax(int v, int lane) {
#pragma unroll
    for (int d = 1; d < 32; d <<= 1) {
        int o = __shfl_up_sync(FULL, v, d);
        if (lane >= d) v = max(v, o);
    }
    return v;
}

__global__ void __launch_bounds__(NT)
loss_fused(const float4* __restrict__ logits, const int* __restrict__ labels,
           float* __restrict__ out, int Bn) {
    const int row  = blockIdx.x;
    const int tid  = threadIdx.x;
    const int lane = tid & 31;
    const int wid  = tid >> 5;
    const int base = tid * CHUNK;

    __shared__ uint32_t s_masks[NT];     // packed per-thread occupancy masks
    __shared__ int      s_agg[32];       // enc warp aggregates
    __shared__ uint32_t s_orw[32];       // warp OR of masks
    __shared__ uint32_t s_has;
    __shared__ float    rs[32], rc[32];
    __shared__ int      s_last;

    // ========== Phase 0: stream own 8 positions; CE + masks in registers ==========
    const float4* lrow = logits + (size_t)row * S_LEN + base;
    const int4*   lab4 = reinterpret_cast<const int4*>(labels + (size_t)row * S_LEN + base);

    uint32_t ceu[CHUNK / 2];             // fp16 CE, 2 per word
    uint32_t plw[2] = {0, 0};            // packed pred|lb<<2|valid<<4 bytes
    uint32_t mT2 = 0, mT3 = 0, mP2 = 0, mP3 = 0;   // 8-bit occupancy masks
    int enc = -1;                        // (g<<2)|(pred&1)<<1|(lb&1) at last valid g
#pragma unroll
    for (int h = 0; h < 2; h++) {
        float4 v[4];
        int4 la = lab4[h];
        int labs[4] = {la.x, la.y, la.z, la.w};
#pragma unroll
        for (int j = 0; j < 4; j++) v[j] = lrow[h * 4 + j];   // batched -> MLP
#pragma unroll
        for (int j = 0; j < 4; j++) {
            float x = v[j].x, y = v[j].y, z = v[j].z, w = v[j].w;
            int pred = 0; float m = x;
            if (y > m) { m = y; pred = 1; }
            if (z > m) { m = z; pred = 2; }
            if (w > m) { m = w; pred = 3; }
            int  lab   = labs[j];
            bool valid = (lab != -100);
            int  lb    = valid ? lab : 0;
            float ce = 0.0f;
            if (valid) {
                float e   = __expf(x - m) + __expf(y - m) + __expf(z - m) + __expf(w - m);
                float lse = m + __logf(e);
                float xl  = (lb == 0) ? x : (lb == 1) ? y : (lb == 2) ? z : w;
                ce = (lse - xl) * ((lb >= 2) ? 30.0f : 1.0f);
            }
            int t = h * 4 + j;
            unsigned hu = (unsigned)__half_as_ushort(__float2half(ce));
            if (t & 1) ceu[t >> 1] |= hu << 16; else ceu[t >> 1] = hu;
            plw[h] |= ((unsigned)(pred | (lb << 2) | (valid ? 16 : 0))) << (j * 8);
            if (valid) enc = ((base + t) << 2) | ((pred & 1) << 1) | (lb & 1);
            if (lb == 2)   mT2 |= 1u << t;
            if (lb == 3)   mT3 |= 1u << t;
            if (pred == 2) mP2 |= 1u << t;
            if (pred == 3) mP3 |= 1u << t;
        }
    }
    uint32_t mW = mT2 | (mT3 << 8) | (mP2 << 16) | (mP3 << 24);

    // ========== Phase 1: mask exchange + has-flags + single enc scan ==========
    s_masks[tid] = mW;
    // enc prefix scan (warp level)
    int incl = warpInclMax(enc, lane);
    int exw  = __shfl_up_sync(FULL, incl, 1);
    int exEnc = (lane == 0) ? -1 : exw;
    if (lane == 31) s_agg[wid] = incl;
    // warp OR of masks for has-flags
    uint32_t wor = __reduce_or_sync(FULL, mW);
    if (lane == 0) s_orw[wid] = wor;
    __syncthreads();

    uint32_t prevW = (tid > 0)      ? s_masks[tid - 1] : 0u;
    uint32_t nextW = (tid < NT - 1) ? s_masks[tid + 1] : 0u;

    // cross-warp enc scan (redundant in every warp)
    int a  = s_agg[lane];
    int ai = warpInclMax(a, lane);
    int c  = __shfl_sync(FULL, ai, (wid == 0) ? 0 : (wid - 1));
    int myExc = max(exEnc, (wid == 0) ? -1 : c);

    if (wid == 0) {
        uint32_t o = __reduce_or_sync(FULL, s_orw[lane]);
        if (lane == 0) s_has = o;
    }
    __syncthreads();
    uint32_t hasW = s_has;
    bool hasT2 = (hasW & 0xffu)        != 0;
    bool hasT3 = (hasW & 0xff00u)      != 0;
    bool hasP2 = (hasW & 0xff0000u)    != 0;
    bool hasP3 = (hasW & 0xff000000u)  != 0;

    // 24-bit windows: [prev 8 | own 8 | next 8]
    uint32_t wT2 = ( prevW        & 0xffu) | ((mW & 0xffu)              << 8) | (( nextW        & 0xffu) << 16);
    uint32_t wT3 = ((prevW >>  8) & 0xffu) | (((mW >>  8) & 0xffu)      << 8) | (((nextW >>  8) & 0xffu) << 16);
    uint32_t wP2 = ((prevW >> 16) & 0xffu) | (((mW >> 16) & 0xffu)      << 8) | (((nextW >> 16) & 0xffu) << 16);
    uint32_t wP3 = ((prevW >> 24) & 0xffu) | (((mW >> 24) & 0xffu)      << 8) | (((nextW >> 24) & 0xffu) << 16);

    // ========== Phase 2: forward walk (state machine + window distances) ==========
    int pm = (myExc < 0) ? 0 : ((myExc >> 1) & 1);
    int tm = (myExc < 0) ? 0 : (myExc & 1);
    float acc = 0.0f;
#pragma unroll
    for (int t = 0; t < CHUNK; t++) {
        unsigned pb = (plw[t >> 2] >> ((t & 3) * 8)) & 0xffu;
        int pred = pb & 3, lb = (pb >> 2) & 3;
        bool valid = (pb & 16) != 0;
        const int p = 8 + t;
        float mult = 1.0f;
        if (valid) {
            if ((pred == 2 && pm == 0) || (pred == 3 && pm == 1)) mult = 100.0f;  // INV_PEN
            if ((lb == 2 && tm == 1 && pred == 2) ||
                (lb == 3 && tm == 0 && pred == 3)) mult *= 0.1f;                  // bonus
        }
        if (pred >= 2) {
            uint32_t w = (pred == 2) ? wT2 : wT3;
            bool has   = (pred == 2) ? hasT2 : hasT3;
            unsigned mb = w & ((2u << p) - 1);
            int dback = p - (31 - __clz(mb));            // mb==0 -> p+1 >= 9 (>5 bucket)
            int dfwd  = __ffs((w >> p) | (1u << 24)) - 1;
            int d = min(dback, dfwd);
            float mp = !has ? 20.0f
                     : (d == 0) ? 0.1f
                     : (d <= 5) ? exp2f((float)d * -0.51457317f)   // 0.7^d
                     : 10.0f;
            mult *= mp;
        }
        if (lb >= 2) {   // implies valid
            uint32_t w = (lb == 2) ? wP2 : wP3;
            bool has   = (lb == 2) ? hasP2 : hasP3;
            unsigned mb = w & ((2u << p) - 1);
            int dback = p - (31 - __clz(mb));
            int dfwd  = __ffs((w >> p) | (1u << 24)) - 1;
            int d = min(dback, dfwd);
            mult *= !has ? 3.0f : ((d > 5) ? 2.0f : 1.0f);
        }
        if (valid) {
            float ce = __half2float(__ushort_as_half(
                (unsigned short)((ceu[t >> 1] >> ((t & 1) * 16)) & 0xffffu)));
            acc += ce * mult;
            pm = pred & 1;
            tm = lb & 1;
        }
    }
    int cnt = __popc(plw[0] & 0x10101010u) + __popc(plw[1] & 0x10101010u);

    // ========== Block reduction (warp shuffles, deterministic) ==========
#pragma unroll
    for (int d = 16; d > 0; d >>= 1) {
        acc += __shfl_down_sync(FULL, acc, d);
        cnt += __shfl_down_sync(FULL, cnt, d);
    }
    if (lane == 0) { rs[wid] = acc; rc[wid] = (float)cnt; }
    __syncthreads();
    if (wid == 0) {
        float a2 = rs[lane], c2 = rc[lane];
#pragma unroll
        for (int d = 16; d > 0; d >>= 1) {
            a2 += __shfl_down_sync(FULL, a2, d);
            c2 += __shfl_down_sync(FULL, c2, d);
        }
        if (lane == 0) {
            g_sum[row] = a2;
            g_cnt[row] = c2;
            __threadfence();
            int old = atomicAdd(&g_ctr, 1);
            s_last = (old == Bn - 1) ? 1 : 0;
        }
    }
    __syncthreads();

    // ========== Last-CTA global reduction (deterministic order) ==========
    if (s_last) {
        __threadfence();
        float ls = 0.0f, lc = 0.0f;
        for (int r = tid; r < Bn; r += NT) { ls += g_sum[r]; lc += g_cnt[r]; }
#pragma unroll
        for (int d = 16; d > 0; d >>= 1) {
            ls += __shfl_down_sync(FULL, ls, d);
            lc += __shfl_down_sync(FULL, lc, d);
        }
        __syncthreads();
        if (lane == 0) { rs[wid] = ls; rc[wid] = lc; }
        __syncthreads();
        if (wid == 0) {
            float a2 = rs[lane], c2 = rc[lane];
#pragma unroll
            for (int d = 16; d > 0; d >>= 1) {
                a2 += __shfl_down_sync(FULL, a2, d);
                c2 += __shfl_down_sync(FULL, c2, d);
            }
            if (lane == 0) {
                out[0] = a2 / fmaxf(c2, 1.0f);
                g_ctr = 0;   // reset for next graph replay
            }
        }
    }
}

extern "C" void kernel_launch(void* const* d_in, const int* in_sizes, int n_in,
                              void* d_out, int out_size) {
    const float* logits = (const float*)d_in[0];
    const int*   labels = (const int*)d_in[1];
    int Bn = in_sizes[1] / S_LEN;
    if (Bn > B_MAX) Bn = B_MAX;
    loss_fused<<<Bn, NT>>>((const float4*)logits, labels, (float*)d_out, Bn);
}